// round 1
// baseline (speedup 1.0000x reference)
#include <cuda_runtime.h>
#include <cstddef>

namespace {
constexpr int Bn  = 1024;
constexpr int Tn  = 512;
constexpr int Hn  = 64;
constexpr int Gn  = 256;   // 4*H gates
constexpr int IN0 = 22;    // layer-0 input dim
constexpr int IN0P = 24;   // padded to even+aligned
constexpr int CH  = 16;    // x chunk (timesteps) staged per reload
constexpr int NB  = 8;     // batch rows per block  -> grid = 128
}

// Inter-layer hidden sequences, [t][b][h] layout (coalesced per-step).
__device__ float g_seq0[(size_t)Tn * Bn * Hn];
__device__ float g_seq1[(size_t)Tn * Bn * Hn];

using u64 = unsigned long long;

__device__ __forceinline__ u64 fma2(u64 a, u64 b, u64 c) {
    u64 d;
    asm("fma.rn.f32x2 %0, %1, %2, %3;" : "=l"(d) : "l"(a), "l"(b), "l"(c));
    return d;
}
__device__ __forceinline__ u64 pack2(float lo, float hi) {
    return ((u64)__float_as_uint(hi) << 32) | (u64)__float_as_uint(lo);
}
__device__ __forceinline__ float hadd2(u64 a) {
    return __uint_as_float((unsigned)a) + __uint_as_float((unsigned)(a >> 32));
}
__device__ __forceinline__ float sigm(float x) {
    return __fdividef(1.f, 1.f + __expf(-x));
}
__device__ __forceinline__ float tanh_(float x) {
    return __fdividef(2.f, 1.f + __expf(-2.f * x)) - 1.f;
}

// One LSTM layer. Each block owns NB batch rows for all T steps.
// Thread g (0..255) computes gate g's pre-activation for all NB rows
// using register-resident weight rows packed as f32x2 pairs.
// Combine phase is spread over all 256 threads (cell = g&63, rows g>>6 and g>>6+4).
template<int LAYER>
__global__ void __launch_bounds__(256, 1)
lstm_layer_k(const float* __restrict__ xin,
             const float* __restrict__ w_ih, const float* __restrict__ w_hh,
             const float* __restrict__ b_ih, const float* __restrict__ b_hh,
             const float* __restrict__ w_fc, const float* __restrict__ b_fc,
             float* __restrict__ out_fc)
{
    constexpr bool FIRST = (LAYER == 0);
    constexpr bool LAST  = (LAYER == 2);
    constexpr int DIN   = FIRST ? IN0  : Hn;
    constexpr int DINP  = FIRST ? IN0P : Hn;
    constexpr int INLEN = DINP + Hn;       // concat(x_t, h_{t-1}) per row
    constexpr int NPAIR = INLEN / 2;

    const float* in;
    if constexpr (LAYER == 0)      in = xin;
    else if constexpr (LAYER == 1) in = g_seq0;
    else                           in = g_seq1;
    float* outs;
    if constexpr (LAYER == 0)      outs = g_seq0;
    else if constexpr (LAYER == 1) outs = g_seq1;
    else                           outs = nullptr;

    const int g  = threadIdx.x;            // gate index 0..255
    const int b0 = blockIdx.x * NB;

    __shared__ __align__(16) float in_s[NB][INLEN];      // [x_t | h]
    __shared__ float gates_s[NB][Gn];
    __shared__ float xc[FIRST ? NB * IN0 * CH : 1];      // layer-0 x chunk

    // ---- load this gate's weight rows into registers as f32x2 pairs ----
    u64 w2[NPAIR];
#pragma unroll
    for (int p = 0; p < DINP / 2; p++) {
        float lo = (2 * p     < DIN) ? w_ih[g * DIN + 2 * p]     : 0.f;
        float hi = (2 * p + 1 < DIN) ? w_ih[g * DIN + 2 * p + 1] : 0.f;
        w2[p] = pack2(lo, hi);
    }
#pragma unroll
    for (int p = 0; p < Hn / 2; p++)
        w2[DINP / 2 + p] = pack2(w_hh[g * Hn + 2 * p], w_hh[g * Hn + 2 * p + 1]);
    const float bias = b_ih[g] + b_hh[g];

    // zero smem (h starts at 0; pads stay 0)
    for (int e = g; e < NB * INLEN; e += 256)
        (&in_s[0][0])[e] = 0.f;

    float cst[NB / 4];
#pragma unroll
    for (int p = 0; p < NB / 4; p++) cst[p] = 0.f;
    const int cell  = g & 63;
    const int rbase = g >> 6;

    for (int t = 0; t < Tn; t++) {
        // ---- stage input x_t for all NB rows ----
        if constexpr (FIRST) {
            const int tt = t & (CH - 1);
            if (tt == 0) {
                for (int e = g; e < NB * IN0 * CH; e += 256) {
                    int r = e / (IN0 * CH);
                    int rem = e - r * (IN0 * CH);
                    int i = rem / CH;
                    int j = rem - i * CH;
                    xc[e] = in[(size_t)(b0 + r) * (IN0 * Tn) + i * Tn + t + j];
                }
                __syncthreads();
            }
            if (g < NB * IN0P) {
                int r = g / IN0P;
                int i = g - r * IN0P;
                in_s[r][i] = (i < IN0) ? xc[r * (IN0 * CH) + i * CH + tt] : 0.f;
            }
        } else {
            for (int e = g; e < NB * Hn; e += 256) {
                int r = e >> 6;
                int k = e & 63;
                in_s[r][k] = in[((size_t)t * Bn + b0 + r) * Hn + k];
            }
        }
        __syncthreads();   // S1: x staged + previous h visible

        // ---- phase A: gate pre-activations (f32x2 FMA, LDS.128 broadcast) ----
        u64 acc0[NB], acc1[NB];
#pragma unroll
        for (int r = 0; r < NB; r++) { acc0[r] = pack2(bias, 0.f); acc1[r] = 0ull; }
#pragma unroll
        for (int q = 0; q < NPAIR / 2; q++) {
#pragma unroll
            for (int r = 0; r < NB; r++) {
                ulonglong2 v = reinterpret_cast<const ulonglong2*>(&in_s[r][0])[q];
                acc0[r] = fma2(w2[2 * q],     v.x, acc0[r]);
                acc1[r] = fma2(w2[2 * q + 1], v.y, acc1[r]);
            }
        }
#pragma unroll
        for (int r = 0; r < NB; r++)
            gates_s[r][g] = hadd2(acc0[r]) + hadd2(acc1[r]);

        __syncthreads();   // S2: gates ready

        // ---- combine: activations + state update (all 256 threads) ----
#pragma unroll
        for (int p = 0; p < NB / 4; p++) {
            const int r = rbase + 4 * p;
            float iv = sigm (gates_s[r][cell]);
            float fv = sigm (gates_s[r][64  + cell]);
            float gv = tanh_(gates_s[r][128 + cell]);
            float ov = sigm (gates_s[r][192 + cell]);
            float cc = fv * cst[p] + iv * gv;
            cst[p] = cc;
            float h = ov * tanh_(cc);
            in_s[r][DINP + cell] = h;
            if constexpr (!LAST)
                outs[((size_t)t * Bn + b0 + r) * Hn + cell] = h;
        }
        // next-iteration S1 orders combine writes before phase-A reads
    }

    if constexpr (LAST) {
        __syncthreads();
        // final FC: out[b][o] = h_last . w_fc[o] + b_fc[o]
        if (g < NB * 4) {
            int r = g >> 2;
            int o = g & 3;
            float s = b_fc[o];
#pragma unroll
            for (int k = 0; k < Hn; k++)
                s += in_s[r][DINP + k] * w_fc[o * Hn + k];
            out_fc[(b0 + r) * 4 + o] = s;
        }
    }
}

extern "C" void kernel_launch(void* const* d_in, const int* in_sizes, int n_in,
                              void* d_out, int out_size)
{
    const float* x     = (const float*)d_in[0];
    const float* wih0  = (const float*)d_in[1];
    const float* whh0  = (const float*)d_in[2];
    const float* bih0  = (const float*)d_in[3];
    const float* bhh0  = (const float*)d_in[4];
    const float* wih1  = (const float*)d_in[5];
    const float* whh1  = (const float*)d_in[6];
    const float* bih1  = (const float*)d_in[7];
    const float* bhh1  = (const float*)d_in[8];
    const float* wih2  = (const float*)d_in[9];
    const float* whh2  = (const float*)d_in[10];
    const float* bih2  = (const float*)d_in[11];
    const float* bhh2  = (const float*)d_in[12];
    const float* wfc   = (const float*)d_in[13];
    const float* bfc   = (const float*)d_in[14];
    float* out = (float*)d_out;

    dim3 grid(Bn / NB);   // 128 blocks
    dim3 block(256);

    lstm_layer_k<0><<<grid, block>>>(x,       wih0, whh0, bih0, bhh0, nullptr, nullptr, nullptr);
    lstm_layer_k<1><<<grid, block>>>(nullptr, wih1, whh1, bih1, bhh1, nullptr, nullptr, nullptr);
    lstm_layer_k<2><<<grid, block>>>(nullptr, wih2, whh2, bih2, bhh2, wfc,     bfc,     out);
}

// round 2
// speedup vs baseline: 1.4999x; 1.4999x over previous
#include <cuda_runtime.h>
#include <cstddef>

namespace {
constexpr int Bn  = 1024;
constexpr int Tn  = 512;
constexpr int Hn  = 64;
constexpr int NB  = 8;     // batch rows per block  -> grid = 128
constexpr int NT  = 512;   // threads per block (16 warps)
}

// Inter-layer hidden sequences, [t][b][h] layout (coalesced per-step).
__device__ float g_seq0[(size_t)Tn * Bn * Hn];
__device__ float g_seq1[(size_t)Tn * Bn * Hn];
// Layer-0 input transposed+padded: [t][b][32] (cols 22..31 zero)
__device__ float g_xT[(size_t)Tn * Bn * 32];

using u64 = unsigned long long;

__device__ __forceinline__ u64 fma2(u64 a, u64 b, u64 c) {
    u64 d;
    asm("fma.rn.f32x2 %0, %1, %2, %3;" : "=l"(d) : "l"(a), "l"(b), "l"(c));
    return d;
}
__device__ __forceinline__ u64 pack2(float lo, float hi) {
    return ((u64)__float_as_uint(hi) << 32) | (u64)__float_as_uint(lo);
}
__device__ __forceinline__ float hadd2(u64 a) {
    return __uint_as_float((unsigned)a) + __uint_as_float((unsigned)(a >> 32));
}
__device__ __forceinline__ float sigm(float x) {
    return __fdividef(1.f, 1.f + __expf(-x));
}
__device__ __forceinline__ float tanh_(float x) {
    return __fdividef(2.f, 1.f + __expf(-2.f * x)) - 1.f;
}

// Transpose x[b][22][t] -> g_xT[t][b][0..31] (pad 22..31 with 0).
// One block per (b, 64-step t-chunk). smem tile avoids uncoalesced global access.
__global__ void __launch_bounds__(256)
transpose_x_k(const float* __restrict__ x)
{
    const int b  = blockIdx.x >> 3;
    const int t0 = (blockIdx.x & 7) * 64;
    __shared__ float tile[22][65];
    for (int e = threadIdx.x; e < 22 * 64; e += 256) {
        int i = e / 64, tt = e - i * 64;
        tile[i][tt] = x[(size_t)b * (22 * Tn) + i * Tn + t0 + tt];
    }
    __syncthreads();
    for (int e = threadIdx.x; e < 64 * 32; e += 256) {
        int tt = e >> 5, i = e & 31;
        g_xT[((size_t)(t0 + tt) * Bn + b) * 32 + i] = (i < 22) ? tile[i][tt] : 0.f;
    }
}

// One LSTM layer. Block owns NB=8 batch rows for all T steps.
// Thread (ks = tid>>7, gp = tid&127) computes gates {2gp, 2gp+1} over
// K-quarter ks for all 8 rows (weights register-resident as f32x2 pairs).
// Partial sums reduced through smem; combine thread (r = tid>>6, c = tid&63)
// owns cell (r,c) and its cell-state register across all steps.
template<int LAYER>
__global__ void __launch_bounds__(NT, 1)
lstm_layer_k(const float* __restrict__ w_ih, const float* __restrict__ w_hh,
             const float* __restrict__ b_ih, const float* __restrict__ b_hh,
             const float* __restrict__ w_fc, const float* __restrict__ b_fc,
             float* __restrict__ out_fc)
{
    constexpr bool FIRST = (LAYER == 0);
    constexpr bool LAST  = (LAYER == 2);
    constexpr int DIN   = FIRST ? 22 : Hn;
    constexpr int DINP  = FIRST ? 32 : Hn;      // padded x width
    constexpr int INLEN = DINP + Hn;            // 96 or 128 floats
    constexpr int NPAIR = INLEN / 2;            // 48 or 64 f32x2 pairs
    constexpr int PP    = NPAIR / 4;            // pairs per K-quarter: 12 or 16

    const float* in;
    if constexpr (LAYER == 0)      in = g_xT;
    else if constexpr (LAYER == 1) in = g_seq0;
    else                           in = g_seq1;
    float* outs;
    if constexpr (LAYER == 0)      outs = g_seq0;
    else if constexpr (LAYER == 1) outs = g_seq1;
    else                           outs = nullptr;

    const int tid = threadIdx.x;
    const int ks  = tid >> 7;          // K-quarter 0..3
    const int gp  = tid & 127;         // gate pair
    const int g0  = 2 * gp;
    const int b0  = blockIdx.x * NB;

    __shared__ __align__(16) float in_s[NB][INLEN];   // [x_t | h_{t-1}] per row
    __shared__ float part[NB][4][256];                // K-quarter partial gate sums

    // ---- register-resident weights for 2 gates x PP pairs ----
    u64 w[2][PP];
#pragma unroll
    for (int gg = 0; gg < 2; gg++) {
        const int g = g0 + gg;
#pragma unroll
        for (int pp = 0; pp < PP; pp++) {
            const int p = ks * PP + pp;            // global pair index
            float lo, hi;
            if (p < DINP / 2) {
                const int c0 = 2 * p;
                lo = (c0     < DIN) ? w_ih[g * DIN + c0]     : 0.f;
                hi = (c0 + 1 < DIN) ? w_ih[g * DIN + c0 + 1] : 0.f;
            } else {
                const int c0 = 2 * (p - DINP / 2);
                lo = w_hh[g * Hn + c0];
                hi = w_hh[g * Hn + c0 + 1];
            }
            w[gg][pp] = pack2(lo, hi);
        }
    }
    const u64 binit0 = (ks == 0) ? pack2(b_ih[g0]     + b_hh[g0],     0.f) : 0ull;
    const u64 binit1 = (ks == 0) ? pack2(b_ih[g0 + 1] + b_hh[g0 + 1], 0.f) : 0ull;

    // zero smem input buffer (h starts at 0, x pad stays 0)
    for (int e = tid; e < NB * INLEN; e += NT)
        (&in_s[0][0])[e] = 0.f;

    // staging identity (1 global float per thread per step)
    const bool act = FIRST ? (tid < NB * 32) : true;
    const int  sr  = FIRST ? (tid >> 5) : (tid >> 6);
    const int  si  = FIRST ? (tid & 31) : (tid & 63);

    // combine identity
    const int cr = tid >> 6;
    const int cc = tid & 63;
    float cst = 0.f;

    float xreg = 0.f;
    if (act) xreg = in[((size_t)0 * Bn + b0 + sr) * DINP + si];

    for (int t = 0; t < Tn; t++) {
        if (act) in_s[sr][si] = xreg;
        __syncthreads();    // S1: x staged, h(t-1) visible, part(t-1) reads done

        // ---- phase A: partial gate pre-activations ----
        u64 a0[NB], a1[NB];
#pragma unroll
        for (int r = 0; r < NB; r++) { a0[r] = binit0; a1[r] = binit1; }
        const int qb = ks * (PP / 2);
#pragma unroll
        for (int q = 0; q < PP / 2; q++) {
#pragma unroll
            for (int r = 0; r < NB; r++) {
                ulonglong2 v = reinterpret_cast<const ulonglong2*>(&in_s[r][0])[qb + q];
                a0[r] = fma2(w[0][2 * q],     v.x, a0[r]);
                a0[r] = fma2(w[0][2 * q + 1], v.y, a0[r]);
                a1[r] = fma2(w[1][2 * q],     v.x, a1[r]);
                a1[r] = fma2(w[1][2 * q + 1], v.y, a1[r]);
            }
        }

        // prefetch next step's input (overlaps with tail of FMA phase)
        if (act && t + 1 < Tn)
            xreg = in[((size_t)(t + 1) * Bn + b0 + sr) * DINP + si];

#pragma unroll
        for (int r = 0; r < NB; r++) {
            float2 pv = make_float2(hadd2(a0[r]), hadd2(a1[r]));
            *reinterpret_cast<float2*>(&part[r][ks][g0]) = pv;
        }
        __syncthreads();    // S2: partials ready

        // ---- combine: reduce 4 K-quarters, activations, state update ----
        float gi = 0.f, gf = 0.f, gg = 0.f, go = 0.f;
#pragma unroll
        for (int k2 = 0; k2 < 4; k2++) {
            gi += part[cr][k2][cc];
            gf += part[cr][k2][64  + cc];
            gg += part[cr][k2][128 + cc];
            go += part[cr][k2][192 + cc];
        }
        float iv = sigm(gi), fv = sigm(gf), gv = tanh_(gg), ov = sigm(go);
        cst = fv * cst + iv * gv;
        float h = ov * tanh_(cst);
        in_s[cr][DINP + cc] = h;
        if constexpr (!LAST)
            outs[((size_t)t * Bn + b0 + cr) * Hn + cc] = h;
        // next S1 orders these writes before the next phase A
    }

    if constexpr (LAST) {
        __syncthreads();
        if (tid < NB * 4) {
            const int r = tid >> 2, o = tid & 3;
            float s = b_fc[o];
#pragma unroll
            for (int k = 0; k < Hn; k++)
                s += in_s[r][DINP + k] * w_fc[o * Hn + k];
            out_fc[(b0 + r) * 4 + o] = s;
        }
    }
}

extern "C" void kernel_launch(void* const* d_in, const int* in_sizes, int n_in,
                              void* d_out, int out_size)
{
    const float* x    = (const float*)d_in[0];
    const float* wih0 = (const float*)d_in[1];
    const float* whh0 = (const float*)d_in[2];
    const float* bih0 = (const float*)d_in[3];
    const float* bhh0 = (const float*)d_in[4];
    const float* wih1 = (const float*)d_in[5];
    const float* whh1 = (const float*)d_in[6];
    const float* bih1 = (const float*)d_in[7];
    const float* bhh1 = (const float*)d_in[8];
    const float* wih2 = (const float*)d_in[9];
    const float* whh2 = (const float*)d_in[10];
    const float* bih2 = (const float*)d_in[11];
    const float* bhh2 = (const float*)d_in[12];
    const float* wfc  = (const float*)d_in[13];
    const float* bfc  = (const float*)d_in[14];
    float* out = (float*)d_out;

    transpose_x_k<<<Bn * 8, 256>>>(x);

    dim3 grid(Bn / NB);   // 128 blocks
    dim3 block(NT);       // 512 threads

    lstm_layer_k<0><<<grid, block>>>(wih0, whh0, bih0, bhh0, nullptr, nullptr, nullptr);
    lstm_layer_k<1><<<grid, block>>>(wih1, whh1, bih1, bhh1, nullptr, nullptr, nullptr);
    lstm_layer_k<2><<<grid, block>>>(wih2, whh2, bih2, bhh2, wfc,     bfc,     out);
}